// round 10
// baseline (speedup 1.0000x reference)
#include <cuda_runtime.h>
#include <cstdint>
#include <cstddef>

// ---------------------------------------------------------------------------
// W8A8 dynamic linear — hybrid IMMA + dp4a kernel, 160/96 split, dp4a 8x8.
//   x [M,K] fp32 -> per-row dynamic int8 quant (scale = maxabs/127, >=1e-8)
//   weight [N,K] int8 (harness widens to int32; detected + packed)
//   out [M,N] fp32 = (xq @ wq^T) * x_scale[m] * w_scale[n] + bias[n]
// Static shapes: M=4096, K=4096, N=11008
//
// CTA = 512 threads, 256-wide N tile.
// Warps 0-7  (IMMA, tensor pipe): cols [bn, bn+160), warp n-tile 64x40.
// Warps 8-15 (dp4a, fma pipe):    cols [bn+160, bn+256); 192 threads compute
//   8x8 tiles (12 x 16 groups); the other 64 threads only feed the A stage.
// ---------------------------------------------------------------------------

#define MAXM 4096
#define MAXK 4096
#define MAXN 11008

__device__ int8_t g_xq[(size_t)MAXM * MAXK];          // 16 MB
__device__ float  g_xscale[MAXM];
__device__ int8_t g_wq[(size_t)MAXN * MAXK];          // 43 MB
__device__ int    g_w_widened;

// ------------------------------ helpers ------------------------------------
__device__ __forceinline__ uint32_t smem_u32(const void* p) {
    uint32_t a;
    asm("{ .reg .u64 t; cvta.to.shared.u64 t, %1; cvt.u32.u64 %0, t; }"
        : "=r"(a) : "l"(p));
    return a;
}

__device__ __forceinline__ uint32_t swz(uint32_t o) {   // SW128 swizzle
    return o ^ ((o >> 3) & 0x70);
}

__device__ __forceinline__ void cp_async16(uint32_t dst, const void* src) {
    asm volatile("cp.async.cg.shared.global [%0], [%1], 16;"
                 :: "r"(dst), "l"(src) : "memory");
}
#define CP_ASYNC_COMMIT() asm volatile("cp.async.commit_group;" ::: "memory")
#define CP_ASYNC_WAIT(n)  asm volatile("cp.async.wait_group %0;" :: "n"(n) : "memory")

#define BAR_SYNC(id, cnt) \
    asm volatile("bar.sync %0, %1;" :: "r"(id), "r"(cnt) : "memory")

__device__ __forceinline__ void ldsm_x4(uint32_t& r0, uint32_t& r1,
                                        uint32_t& r2, uint32_t& r3,
                                        uint32_t addr) {
    asm volatile("ldmatrix.sync.aligned.m8n8.x4.shared.b16 {%0,%1,%2,%3}, [%4];"
                 : "=r"(r0), "=r"(r1), "=r"(r2), "=r"(r3) : "r"(addr));
}

__device__ __forceinline__ void ldsm_x2(uint32_t& r0, uint32_t& r1,
                                        uint32_t addr) {
    asm volatile("ldmatrix.sync.aligned.m8n8.x2.shared.b16 {%0,%1}, [%2];"
                 : "=r"(r0), "=r"(r1) : "r"(addr));
}

__device__ __forceinline__ void imma16832(int* d, const uint32_t* a,
                                          const uint32_t* b) {
    asm volatile(
        "mma.sync.aligned.m16n8k32.row.col.s32.s8.s8.s32 "
        "{%0,%1,%2,%3}, {%4,%5,%6,%7}, {%8,%9}, {%0,%1,%2,%3};"
        : "+r"(d[0]), "+r"(d[1]), "+r"(d[2]), "+r"(d[3])
        : "r"(a[0]), "r"(a[1]), "r"(a[2]), "r"(a[3]), "r"(b[0]), "r"(b[1]));
}

// ---------------------------------------------------------------------------
// Kernel 0a: detect weight dtype (int32-widened vs packed int8).
// ---------------------------------------------------------------------------
__global__ void detect_w_dtype(const int* __restrict__ w) {
    int bad = 0;
    for (int i = threadIdx.x; i < 8192; i += 32) {
        int v = w[i];
        bad |= (v < -128 || v > 127) ? 1 : 0;
    }
#pragma unroll
    for (int o = 16; o > 0; o >>= 1)
        bad |= __shfl_xor_sync(0xffffffffu, bad, o);
    if (threadIdx.x == 0) g_w_widened = bad ? 0 : 1;
}

// ---------------------------------------------------------------------------
// Kernel 0b: pack weights int32 -> int8 (or copy if already packed).
// ---------------------------------------------------------------------------
__device__ __forceinline__ int pack4(int4 v) {
    return (v.x & 0xff) | ((v.y & 0xff) << 8) | ((v.z & 0xff) << 16) | (v.w << 24);
}

__global__ __launch_bounds__(256) void pack_w(const int* __restrict__ w,
                                              size_t n_out16) {
    const size_t i = (size_t)blockIdx.x * 256 + threadIdx.x;
    if (i >= n_out16) return;
    int4 outv;
    if (g_w_widened) {
        const int4* src = reinterpret_cast<const int4*>(w) + i * 4;
        outv.x = pack4(src[0]);
        outv.y = pack4(src[1]);
        outv.z = pack4(src[2]);
        outv.w = pack4(src[3]);
    } else {
        outv = reinterpret_cast<const int4*>(w)[i];
    }
    reinterpret_cast<int4*>(g_wq)[i] = outv;
}

// ---------------------------------------------------------------------------
// Kernel 1: per-row maxabs -> scale -> RNE quantize -> pack.
// ---------------------------------------------------------------------------
__global__ __launch_bounds__(256) void quant_rows(const float* __restrict__ x,
                                                  int K) {
    const int m = blockIdx.x;
    const int t = threadIdx.x;
    const int K4 = K >> 2;
    const float4* __restrict__ xrow =
        reinterpret_cast<const float4*>(x + (size_t)m * K);

    float amax = 0.0f;
    for (int i = t; i < K4; i += 256) {
        float4 v = xrow[i];
        amax = fmaxf(amax, fmaxf(fmaxf(fabsf(v.x), fabsf(v.y)),
                                 fmaxf(fabsf(v.z), fabsf(v.w))));
    }

    __shared__ float red[8];
#pragma unroll
    for (int o = 16; o > 0; o >>= 1)
        amax = fmaxf(amax, __shfl_xor_sync(0xffffffffu, amax, o));
    if ((t & 31) == 0) red[t >> 5] = amax;
    __syncthreads();
    if (t < 32) {
        float a = (t < 8) ? red[t] : 0.0f;
#pragma unroll
        for (int o = 4; o > 0; o >>= 1)
            a = fmaxf(a, __shfl_xor_sync(0xffffffffu, a, o));
        if (t == 0) red[0] = a;
    }
    __syncthreads();

    const float scale = fmaxf(red[0] / 127.0f, 1e-8f);
    if (t == 0) g_xscale[m] = scale;

    int* __restrict__ outw = reinterpret_cast<int*>(g_xq + (size_t)m * K);
    for (int i = t; i < K4; i += 256) {
        float4 v = xrow[i];
        int q0 = min(127, max(-128, __float2int_rn(v.x / scale)));
        int q1 = min(127, max(-128, __float2int_rn(v.y / scale)));
        int q2 = min(127, max(-128, __float2int_rn(v.z / scale)));
        int q3 = min(127, max(-128, __float2int_rn(v.w / scale)));
        outw[i] = (q0 & 0xff) | ((q1 & 0xff) << 8) | ((q2 & 0xff) << 16)
                | (q3 << 24);
    }
}

// ---------------------------------------------------------------------------
// Kernel 2: hybrid GEMM, 160 (IMMA) + 96 (dp4a) column split.
// ---------------------------------------------------------------------------
#define NI 160                         // IMMA columns per CTA
#define ND 96                          // dp4a columns per CTA

#define A_TILE (128 * 128)             // 16 KB per A stage
#define B_TILE (NI * 128)              // 20 KB per B stage
#define SM_A0  0
#define SM_B0  (SM_A0 + A_TILE)
#define SM_A1  (SM_B0 + B_TILE)
#define SM_B1  (SM_A1 + A_TILE)
#define SM_D   (SM_B1 + B_TILE)        // dp4a region
#define BKW 8                          // dp4a: int32 words of K per stage
#define SM_DA  SM_D                    // As: [BKW][128] ints = 4 KB
#define SM_DB  (SM_D + BKW * 128 * 4)  // Bs: [BKW][96]  ints = 3 KB
#define SM_TOTAL (SM_DB + BKW * ND * 4)

__global__ __launch_bounds__(512, 1)
void gemm_hybrid(const float* __restrict__ wscale,
                 const float* __restrict__ bias,
                 float* __restrict__ out,
                 int M, int N, int K) {
    extern __shared__ __align__(1024) char smem[];
    const uint32_t sbase = smem_u32(smem);

    const int tid  = threadIdx.x;
    const int bm   = blockIdx.y * 128;
    const int bn_i = blockIdx.x * 256;        // IMMA columns
    const int bn_d = bn_i + NI;               // dp4a columns

    if (tid < 256) {
        // ================= IMMA group (warps 0-7, tensor pipe) =============
        const int t   = tid;
        const int wid = t >> 5;
        const int lid = t & 31;
        const int wm  = wid >> 2;             // 0..1 (m: 64 rows each)
        const int wn  = wid & 3;              // 0..3 (n: 40 cols each)

        const int cg = t & 7;
        const int r0 = t >> 3;                // 0..31
        const int Kw16 = K >> 4;

        const int4* Abase = reinterpret_cast<const int4*>(g_xq) + cg;
        const int4* Bbase = reinterpret_cast<const int4*>(g_wq) + cg;

        uint32_t sA_dst[2][4], sB_dst[2][5];
#pragma unroll
        for (int p = 0; p < 2; p++) {
#pragma unroll
            for (int i = 0; i < 4; i++) {
                const uint32_t o =
                    swz((uint32_t)(r0 + 32 * i) * 128u + (uint32_t)cg * 16u);
                sA_dst[p][i] = sbase + (p ? SM_A1 : SM_A0) + o;
            }
#pragma unroll
            for (int i = 0; i < 5; i++) {
                const uint32_t o =
                    swz((uint32_t)(r0 + 32 * i) * 128u + (uint32_t)cg * 16u);
                sB_dst[p][i] = sbase + (p ? SM_B1 : SM_B0) + o;
            }
        }

        const int nstage = K / 128;           // 32

        auto issue = [&](int kc) {
            const int4* Ag = Abase + (size_t)(kc * 8);
            const int4* Bg = Bbase + (size_t)(kc * 8);
            const int p = kc & 1;
#pragma unroll
            for (int i = 0; i < 4; i++)
                cp_async16(sA_dst[p][i], Ag + (size_t)(bm + r0 + 32 * i) * Kw16);
#pragma unroll
            for (int i = 0; i < 5; i++)
                cp_async16(sB_dst[p][i], Bg + (size_t)(bn_i + r0 + 32 * i) * Kw16);
            CP_ASYNC_COMMIT();
        };

        const int lrow_off = (lid & 7) + ((lid >> 3) & 1) * 8;
        const int lchunk   = lid >> 4;        // x4 chunk selector
        const int l2row    = lid & 7;         // x2 row
        const int l2chunk  = (lid >> 3) & 1;  // x2 chunk selector

        int acc[4][5][4];
#pragma unroll
        for (int i = 0; i < 4; i++)
#pragma unroll
            for (int j = 0; j < 5; j++)
#pragma unroll
                for (int q = 0; q < 4; q++) acc[i][j][q] = 0;

        issue(0);

        for (int kc = 0; kc < nstage; kc++) {
            if (kc + 1 < nstage) {
                issue(kc + 1);
                CP_ASYNC_WAIT(1);
            } else {
                CP_ASYNC_WAIT(0);
            }
            BAR_SYNC(1, 256);

            const int p = kc & 1;
            const uint32_t sA = sbase + (p ? SM_A1 : SM_A0);
            const uint32_t sB = sbase + (p ? SM_B1 : SM_B0);

#pragma unroll
            for (int s = 0; s < 4; s++) {
                const int c = s * 2 + lchunk;
                uint32_t a[4][4];
#pragma unroll
                for (int ma = 0; ma < 4; ma++) {
                    const uint32_t row = (uint32_t)(wm * 64 + ma * 16 + lrow_off);
                    ldsm_x4(a[ma][0], a[ma][1], a[ma][2], a[ma][3],
                            sA + swz(row * 128u + (uint32_t)c * 16u));
                }
                uint32_t b[5][2];
#pragma unroll
                for (int nb = 0; nb < 2; nb++) {
                    const uint32_t row = (uint32_t)(wn * 40 + nb * 16 + lrow_off);
                    uint32_t q0, q1, q2, q3;
                    ldsm_x4(q0, q1, q2, q3,
                            sB + swz(row * 128u + (uint32_t)c * 16u));
                    b[2 * nb][0] = q0; b[2 * nb][1] = q2;
                    b[2 * nb + 1][0] = q1; b[2 * nb + 1][1] = q3;
                }
                {   // last 8 n-rows via x2 (lanes 0-15 supply addresses)
                    const uint32_t row = (uint32_t)(wn * 40 + 32 + l2row);
                    const int c2 = s * 2 + l2chunk;
                    uint32_t q0, q1;
                    ldsm_x2(q0, q1,
                            sB + swz(row * 128u + (uint32_t)c2 * 16u));
                    b[4][0] = q0; b[4][1] = q1;
                }
#pragma unroll
                for (int ma = 0; ma < 4; ma++)
#pragma unroll
                    for (int na = 0; na < 5; na++)
                        imma16832(acc[ma][na], a[ma], b[na]);
            }
            BAR_SYNC(1, 256);
        }

        // epilogue
        const int g = lid >> 2;
        const int q = lid & 3;
#pragma unroll
        for (int ma = 0; ma < 4; ma++) {
            const int m0 = bm + wm * 64 + ma * 16 + g;
            const int m1 = m0 + 8;
            const float xs0 = g_xscale[m0];
            const float xs1 = g_xscale[m1];
            float* row0 = out + (size_t)m0 * N;
            float* row1 = out + (size_t)m1 * N;
#pragma unroll
            for (int na = 0; na < 5; na++) {
                const int n = bn_i + wn * 40 + na * 8 + q * 2;
                const float ws0 = __ldg(wscale + n);
                const float ws1 = __ldg(wscale + n + 1);
                const float bb0 = __ldg(bias + n);
                const float bb1 = __ldg(bias + n + 1);
                float2 o0, o1;
                o0.x = (float)acc[ma][na][0] * xs0 * ws0 + bb0;
                o0.y = (float)acc[ma][na][1] * xs0 * ws1 + bb1;
                o1.x = (float)acc[ma][na][2] * xs1 * ws0 + bb0;
                o1.y = (float)acc[ma][na][3] * xs1 * ws1 + bb1;
                *reinterpret_cast<float2*>(row0 + n) = o0;
                *reinterpret_cast<float2*>(row1 + n) = o1;
            }
        }
    } else {
        // ================= dp4a group (warps 8-15, fma pipe) ===============
        // 128x96 tile. 192 compute threads in 8x8 tiles (12 tx x 16 ty).
        // All 256 threads help fill SMEM stages and hit barriers.
        const int t = tid - 256;

        int* As = reinterpret_cast<int*>(smem + SM_DA);   // [BKW][128]
        int* Bs = reinterpret_cast<int*>(smem + SM_DB);   // [BKW][96]

        const bool comp = (t < 192);
        const int tx = comp ? (t % 12) : 0;   // 0..11 -> 8 cols each
        const int ty = comp ? (t / 12) : 0;   // 0..15 -> 8 rows each

        // Stage fill: A 256 int4 -> all 256 threads, 1 each.
        const int arow  = t >> 1;
        const int ahalf = t & 1;
        // B 192 int4 -> threads 0..191, 1 each.
        const int brow  = t >> 1;
        const int bhalf = t & 1;

        const int Kw16 = K >> 4;
        const int nstage = (K >> 2) / BKW; // 128 stages

        const int4* Ag = reinterpret_cast<const int4*>(g_xq) +
                         (size_t)(bm + arow) * Kw16 + ahalf;
        const int4* Bg = reinterpret_cast<const int4*>(g_wq) +
                         (size_t)(bn_d + brow) * Kw16 + bhalf;

        int acc[8][8];
#pragma unroll
        for (int i = 0; i < 8; i++)
#pragma unroll
            for (int j = 0; j < 8; j++) acc[i][j] = 0;

        int4 pa = Ag[0];
        int4 pb = comp ? Bg[0] : make_int4(0, 0, 0, 0);

        const int wa = ahalf * 4;
        const int wb = bhalf * 4;

        for (int s = 0; s < nstage; s++) {
            BAR_SYNC(2, 256);              // previous stage's reads done

            As[(wa + 0) * 128 + arow] = pa.x;
            As[(wa + 1) * 128 + arow] = pa.y;
            As[(wa + 2) * 128 + arow] = pa.z;
            As[(wa + 3) * 128 + arow] = pa.w;
            if (comp) {
                Bs[(wb + 0) * 96 + brow] = pb.x;
                Bs[(wb + 1) * 96 + brow] = pb.y;
                Bs[(wb + 2) * 96 + brow] = pb.z;
                Bs[(wb + 3) * 96 + brow] = pb.w;
            }

            if (s + 1 < nstage) {
                pa = Ag[(size_t)(s + 1) * 2];
                if (comp) pb = Bg[(size_t)(s + 1) * 2];
            }

            BAR_SYNC(2, 256);              // stores visible

            if (comp) {
#pragma unroll
                for (int kk = 0; kk < BKW; kk++) {
                    int4 af0 = *reinterpret_cast<const int4*>(&As[kk * 128 + (ty << 3)]);
                    int4 af1 = *reinterpret_cast<const int4*>(&As[kk * 128 + (ty << 3) + 4]);
                    int4 bf0 = *reinterpret_cast<const int4*>(&Bs[kk * 96 + (tx << 3)]);
                    int4 bf1 = *reinterpret_cast<const int4*>(&Bs[kk * 96 + (tx << 3) + 4]);
                    int af[8] = {af0.x, af0.y, af0.z, af0.w, af1.x, af1.y, af1.z, af1.w};
                    int bf[8] = {bf0.x, bf0.y, bf0.z, bf0.w, bf1.x, bf1.y, bf1.z, bf1.w};
#pragma unroll
                    for (int i = 0; i < 8; i++)
#pragma unroll
                        for (int j = 0; j < 8; j++)
                            acc[i][j] = __dp4a(af[i], bf[j], acc[i][j]);
                }
            }
        }

        if (comp) {
            const int cn = bn_d + (tx << 3);
            float4 ws0 = *reinterpret_cast<const float4*>(wscale + cn);
            float4 ws1 = *reinterpret_cast<const float4*>(wscale + cn + 4);
            float4 bb0 = *reinterpret_cast<const float4*>(bias + cn);
            float4 bb1 = *reinterpret_cast<const float4*>(bias + cn + 4);
            float wsc[8] = {ws0.x, ws0.y, ws0.z, ws0.w, ws1.x, ws1.y, ws1.z, ws1.w};
            float bb[8]  = {bb0.x, bb0.y, bb0.z, bb0.w, bb1.x, bb1.y, bb1.z, bb1.w};

#pragma unroll
            for (int i = 0; i < 8; i++) {
                const int m = bm + (ty << 3) + i;
                const float xs = g_xscale[m];
                float* orow = out + (size_t)m * N + cn;
                float4 o0, o1;
                o0.x = (float)acc[i][0] * xs * wsc[0] + bb[0];
                o0.y = (float)acc[i][1] * xs * wsc[1] + bb[1];
                o0.z = (float)acc[i][2] * xs * wsc[2] + bb[2];
                o0.w = (float)acc[i][3] * xs * wsc[3] + bb[3];
                o1.x = (float)acc[i][4] * xs * wsc[4] + bb[4];
                o1.y = (float)acc[i][5] * xs * wsc[5] + bb[5];
                o1.z = (float)acc[i][6] * xs * wsc[6] + bb[6];
                o1.w = (float)acc[i][7] * xs * wsc[7] + bb[7];
                *reinterpret_cast<float4*>(orow)     = o0;
                *reinterpret_cast<float4*>(orow + 4) = o1;
            }
        }
    }
}

// ---------------------------------------------------------------------------
// Launch
// ---------------------------------------------------------------------------
extern "C" void kernel_launch(void* const* d_in, const int* in_sizes, int n_in,
                              void* d_out, int out_size) {
    const float* x      = (const float*)d_in[0];
    const int*   weight = (const int*)d_in[1];
    const float* wscale = (const float*)d_in[2];
    const float* bias   = (const float*)d_in[3];
    float*       out    = (float*)d_out;

    const int N = in_sizes[2];           // 11008
    const int K = in_sizes[1] / N;       // 4096
    const int M = in_sizes[0] / K;       // 4096

    detect_w_dtype<<<1, 32>>>(weight);

    const size_t n_out16 = ((size_t)N * K) / 16;
    pack_w<<<(unsigned)((n_out16 + 255) / 256), 256>>>(weight, n_out16);

    quant_rows<<<M, 256>>>(x, K);

    static bool smem_set = false;
    if (!smem_set) {
        cudaFuncSetAttribute(gemm_hybrid,
                             cudaFuncAttributeMaxDynamicSharedMemorySize,
                             SM_TOTAL);
        smem_set = true;
    }
    dim3 grid(N / 256, M / 128);         // 43 x 32
    gemm_hybrid<<<grid, 512, SM_TOTAL>>>(wscale, bias, out, M, N, K);
}

// round 11
// speedup vs baseline: 1.1600x; 1.1600x over previous
#include <cuda_runtime.h>
#include <cstdint>
#include <cstddef>

// ---------------------------------------------------------------------------
// W8A8 dynamic linear — persistent hybrid IMMA + dp4a kernel.
//   x [M,K] fp32 -> per-row dynamic int8 quant (scale = maxabs/127, >=1e-8)
//   weight [N,K] int8 (harness widens to int32; detected + packed)
//   out [M,N] fp32 = (xq @ wq^T) * x_scale[m] * w_scale[n] + bias[n]
// Static shapes: M=4096, K=4096, N=11008.
//
// Grid = #SMs, 512 threads/CTA, 1 CTA/SM (full RF). Within each CTA:
//   warps 0-7  (IMMA, tensor pipe) loop over jobs from the IMMA tile pool
//   warps 8-15 (dp4a, fma pipe)    loop over jobs from the dp4a tile pool
// Each job is a full 128x128 output tile — microkernels identical to the
// proven R8 shapes. Pool split 51/35 of 86 n-tiles = measured 1830:1254
// per-tile cost ratio, so both halves finish together.
// ---------------------------------------------------------------------------

#define MAXM 4096
#define MAXK 4096
#define MAXN 11008

#define M_TILES 32                     // M/128
#define N_TILES 86                     // N/128
#define NTI 51                         // IMMA pool n-tiles
#define NTD (N_TILES - NTI)            // dp4a pool n-tiles (35)

__device__ int8_t g_xq[(size_t)MAXM * MAXK];          // 16 MB
__device__ float  g_xscale[MAXM];
__device__ int8_t g_wq[(size_t)MAXN * MAXK];          // 43 MB
__device__ int    g_w_widened;

// ------------------------------ helpers ------------------------------------
__device__ __forceinline__ uint32_t smem_u32(const void* p) {
    uint32_t a;
    asm("{ .reg .u64 t; cvta.to.shared.u64 t, %1; cvt.u32.u64 %0, t; }"
        : "=r"(a) : "l"(p));
    return a;
}

__device__ __forceinline__ uint32_t swz(uint32_t o) {   // SW128 swizzle
    return o ^ ((o >> 3) & 0x70);
}

__device__ __forceinline__ void cp_async16(uint32_t dst, const void* src) {
    asm volatile("cp.async.cg.shared.global [%0], [%1], 16;"
                 :: "r"(dst), "l"(src) : "memory");
}
#define CP_ASYNC_COMMIT() asm volatile("cp.async.commit_group;" ::: "memory")
#define CP_ASYNC_WAIT(n)  asm volatile("cp.async.wait_group %0;" :: "n"(n) : "memory")

#define BAR_SYNC(id, cnt) \
    asm volatile("bar.sync %0, %1;" :: "r"(id), "r"(cnt) : "memory")

__device__ __forceinline__ void ldsm_x4(uint32_t& r0, uint32_t& r1,
                                        uint32_t& r2, uint32_t& r3,
                                        uint32_t addr) {
    asm volatile("ldmatrix.sync.aligned.m8n8.x4.shared.b16 {%0,%1,%2,%3}, [%4];"
                 : "=r"(r0), "=r"(r1), "=r"(r2), "=r"(r3) : "r"(addr));
}

__device__ __forceinline__ void imma16832(int* d, const uint32_t* a,
                                          const uint32_t* b) {
    asm volatile(
        "mma.sync.aligned.m16n8k32.row.col.s32.s8.s8.s32 "
        "{%0,%1,%2,%3}, {%4,%5,%6,%7}, {%8,%9}, {%0,%1,%2,%3};"
        : "+r"(d[0]), "+r"(d[1]), "+r"(d[2]), "+r"(d[3])
        : "r"(a[0]), "r"(a[1]), "r"(a[2]), "r"(a[3]), "r"(b[0]), "r"(b[1]));
}

// ---------------------------------------------------------------------------
// Kernel 0a: detect weight dtype (int32-widened vs packed int8).
// ---------------------------------------------------------------------------
__global__ void detect_w_dtype(const int* __restrict__ w) {
    int bad = 0;
    for (int i = threadIdx.x; i < 8192; i += 32) {
        int v = w[i];
        bad |= (v < -128 || v > 127) ? 1 : 0;
    }
#pragma unroll
    for (int o = 16; o > 0; o >>= 1)
        bad |= __shfl_xor_sync(0xffffffffu, bad, o);
    if (threadIdx.x == 0) g_w_widened = bad ? 0 : 1;
}

// ---------------------------------------------------------------------------
// Kernel 0b: pack weights int32 -> int8 (or copy if already packed).
// ---------------------------------------------------------------------------
__device__ __forceinline__ int pack4(int4 v) {
    return (v.x & 0xff) | ((v.y & 0xff) << 8) | ((v.z & 0xff) << 16) | (v.w << 24);
}

__global__ __launch_bounds__(256) void pack_w(const int* __restrict__ w,
                                              size_t n_out16) {
    const size_t i = (size_t)blockIdx.x * 256 + threadIdx.x;
    if (i >= n_out16) return;
    int4 outv;
    if (g_w_widened) {
        const int4* src = reinterpret_cast<const int4*>(w) + i * 4;
        outv.x = pack4(src[0]);
        outv.y = pack4(src[1]);
        outv.z = pack4(src[2]);
        outv.w = pack4(src[3]);
    } else {
        outv = reinterpret_cast<const int4*>(w)[i];
    }
    reinterpret_cast<int4*>(g_wq)[i] = outv;
}

// ---------------------------------------------------------------------------
// Kernel 1: per-row maxabs -> scale -> RNE quantize -> pack.
// ---------------------------------------------------------------------------
__global__ __launch_bounds__(256) void quant_rows(const float* __restrict__ x,
                                                  int K) {
    const int m = blockIdx.x;
    const int t = threadIdx.x;
    const int K4 = K >> 2;
    const float4* __restrict__ xrow =
        reinterpret_cast<const float4*>(x + (size_t)m * K);

    float amax = 0.0f;
    for (int i = t; i < K4; i += 256) {
        float4 v = xrow[i];
        amax = fmaxf(amax, fmaxf(fmaxf(fabsf(v.x), fabsf(v.y)),
                                 fmaxf(fabsf(v.z), fabsf(v.w))));
    }

    __shared__ float red[8];
#pragma unroll
    for (int o = 16; o > 0; o >>= 1)
        amax = fmaxf(amax, __shfl_xor_sync(0xffffffffu, amax, o));
    if ((t & 31) == 0) red[t >> 5] = amax;
    __syncthreads();
    if (t < 32) {
        float a = (t < 8) ? red[t] : 0.0f;
#pragma unroll
        for (int o = 4; o > 0; o >>= 1)
            a = fmaxf(a, __shfl_xor_sync(0xffffffffu, a, o));
        if (t == 0) red[0] = a;
    }
    __syncthreads();

    const float scale = fmaxf(red[0] / 127.0f, 1e-8f);
    if (t == 0) g_xscale[m] = scale;

    int* __restrict__ outw = reinterpret_cast<int*>(g_xq + (size_t)m * K);
    for (int i = t; i < K4; i += 256) {
        float4 v = xrow[i];
        int q0 = min(127, max(-128, __float2int_rn(v.x / scale)));
        int q1 = min(127, max(-128, __float2int_rn(v.y / scale)));
        int q2 = min(127, max(-128, __float2int_rn(v.z / scale)));
        int q3 = min(127, max(-128, __float2int_rn(v.w / scale)));
        outw[i] = (q0 & 0xff) | ((q1 & 0xff) << 8) | ((q2 & 0xff) << 16)
                | (q3 << 24);
    }
}

// ---------------------------------------------------------------------------
// Kernel 2: persistent hybrid GEMM.
// SMEM: [0,64K) IMMA double-buffered tiles; [64K,72K) dp4a stage buffers.
// ---------------------------------------------------------------------------
#define TILE_BYTES (128 * 128)         // 16 KB
#define SM_A0  0
#define SM_B0  (SM_A0 + TILE_BYTES)
#define SM_A1  (SM_B0 + TILE_BYTES)
#define SM_B1  (SM_A1 + TILE_BYTES)
#define SM_D   (SM_B1 + TILE_BYTES)    // dp4a region: 2 x 4 KB
#define SM_TOTAL (SM_D + 8192)

#define BKW 8    // dp4a: int32 words of K per stage (= 32 int8)

__global__ __launch_bounds__(512, 1)
void gemm_hybrid(const float* __restrict__ wscale,
                 const float* __restrict__ bias,
                 float* __restrict__ out,
                 int M, int N, int K) {
    extern __shared__ __align__(1024) char smem[];
    const uint32_t sbase = smem_u32(smem);

    const int tid  = threadIdx.x;
    const int bid  = blockIdx.x;
    const int grid = gridDim.x;

    if (tid < 256) {
        // ================= IMMA half (warps 0-7, tensor pipe) ==============
        const int t   = tid;
        const int wid = t >> 5;
        const int lid = t & 31;
        const int wm  = wid >> 2;             // 0..1
        const int wn  = wid & 3;              // 0..3

        const int cg = t & 7;
        const int r0 = t >> 3;
        const int Kw16 = K >> 4;

        const int4* Abase = reinterpret_cast<const int4*>(g_xq) + cg;
        const int4* Bbase = reinterpret_cast<const int4*>(g_wq) + cg;

        uint32_t sA_dst[2][4], sB_dst[2][4];
#pragma unroll
        for (int p = 0; p < 2; p++)
#pragma unroll
            for (int i = 0; i < 4; i++) {
                const uint32_t o =
                    swz((uint32_t)(r0 + 32 * i) * 128u + (uint32_t)cg * 16u);
                sA_dst[p][i] = sbase + (p ? SM_A1 : SM_A0) + o;
                sB_dst[p][i] = sbase + (p ? SM_B1 : SM_B0) + o;
            }

        const int nstage = K / 128;           // 32
        const int lrow_off = (lid & 7) + ((lid >> 3) & 1) * 8;
        const int lchunk   = lid >> 4;
        const int g   = lid >> 2;
        const int q   = lid & 3;

        int bm = 0, bn = 0;
        auto issue = [&](int kc) {
            const int4* Ag = Abase + (size_t)(kc * 8);
            const int4* Bg = Bbase + (size_t)(kc * 8);
            const int p = kc & 1;
#pragma unroll
            for (int i = 0; i < 4; i++) {
                cp_async16(sA_dst[p][i], Ag + (size_t)(bm + r0 + 32 * i) * Kw16);
                cp_async16(sB_dst[p][i], Bg + (size_t)(bn + r0 + 32 * i) * Kw16);
            }
            CP_ASYNC_COMMIT();
        };

        for (int j = bid; j < NTI * M_TILES; j += grid) {
            bm = (j & (M_TILES - 1)) * 128;
            bn = (j >> 5) * 128;              // n-tile 0..NTI-1

            int acc[4][4][4];
#pragma unroll
            for (int i = 0; i < 4; i++)
#pragma unroll
                for (int jj = 0; jj < 4; jj++)
#pragma unroll
                    for (int qq = 0; qq < 4; qq++) acc[i][jj][qq] = 0;

            issue(0);

            for (int kc = 0; kc < nstage; kc++) {
                if (kc + 1 < nstage) {
                    issue(kc + 1);
                    CP_ASYNC_WAIT(1);
                } else {
                    CP_ASYNC_WAIT(0);
                }
                BAR_SYNC(1, 256);

                const int p = kc & 1;
                const uint32_t sA = sbase + (p ? SM_A1 : SM_A0);
                const uint32_t sB = sbase + (p ? SM_B1 : SM_B0);

#pragma unroll
                for (int s = 0; s < 4; s++) {
                    const int c = s * 2 + lchunk;
                    uint32_t a[4][4];
#pragma unroll
                    for (int ma = 0; ma < 4; ma++) {
                        const uint32_t row =
                            (uint32_t)(wm * 64 + ma * 16 + lrow_off);
                        ldsm_x4(a[ma][0], a[ma][1], a[ma][2], a[ma][3],
                                sA + swz(row * 128u + (uint32_t)c * 16u));
                    }
                    uint32_t b[4][2];
#pragma unroll
                    for (int nb = 0; nb < 2; nb++) {
                        const uint32_t row =
                            (uint32_t)(wn * 32 + nb * 16 + lrow_off);
                        uint32_t q0, q1, q2, q3;
                        ldsm_x4(q0, q1, q2, q3,
                                sB + swz(row * 128u + (uint32_t)c * 16u));
                        b[2 * nb][0] = q0; b[2 * nb][1] = q2;
                        b[2 * nb + 1][0] = q1; b[2 * nb + 1][1] = q3;
                    }
#pragma unroll
                    for (int ma = 0; ma < 4; ma++)
#pragma unroll
                        for (int na = 0; na < 4; na++)
                            imma16832(acc[ma][na], a[ma], b[na]);
                }
                BAR_SYNC(1, 256);
            }

            // epilogue
#pragma unroll
            for (int ma = 0; ma < 4; ma++) {
                const int m0 = bm + wm * 64 + ma * 16 + g;
                const int m1 = m0 + 8;
                const float xs0 = g_xscale[m0];
                const float xs1 = g_xscale[m1];
                float* row0 = out + (size_t)m0 * N;
                float* row1 = out + (size_t)m1 * N;
#pragma unroll
                for (int na = 0; na < 4; na++) {
                    const int n = bn + wn * 32 + na * 8 + q * 2;
                    const float ws0 = __ldg(wscale + n);
                    const float ws1 = __ldg(wscale + n + 1);
                    const float bb0 = __ldg(bias + n);
                    const float bb1 = __ldg(bias + n + 1);
                    float2 o0, o1;
                    o0.x = (float)acc[ma][na][0] * xs0 * ws0 + bb0;
                    o0.y = (float)acc[ma][na][1] * xs0 * ws1 + bb1;
                    o1.x = (float)acc[ma][na][2] * xs1 * ws0 + bb0;
                    o1.y = (float)acc[ma][na][3] * xs1 * ws1 + bb1;
                    *reinterpret_cast<float2*>(row0 + n) = o0;
                    *reinterpret_cast<float2*>(row1 + n) = o1;
                }
            }
        }
    } else {
        // ================= dp4a half (warps 8-15, fma pipe) ================
        const int t = tid - 256;

        int* As = reinterpret_cast<int*>(smem + SM_D);          // [BKW][128]
        int* Bs = As + BKW * 128;                               // [BKW][128]

        const int tx = t & 15;
        const int ty = t >> 4;
        const int lrow = t & 127;          // SMEM row this thread fills
        const int cgd  = t >> 7;           // 0/1: 16B group
        const int wa   = cgd * 4;

        const int Kw16 = K >> 4;
        const int nstage = (K >> 2) / BKW; // 128 stages

        for (int j = bid; j < NTD * M_TILES; j += grid) {
            const int bm   = (j & (M_TILES - 1)) * 128;
            const int bn_d = (NTI + (j >> 5)) * 128;

            const int4* Ag = reinterpret_cast<const int4*>(g_xq) +
                             (size_t)(bm + lrow) * Kw16 + cgd;
            const int4* Bg = reinterpret_cast<const int4*>(g_wq) +
                             (size_t)(bn_d + lrow) * Kw16 + cgd;

            int acc[8][8];
#pragma unroll
            for (int i = 0; i < 8; i++)
#pragma unroll
                for (int jj = 0; jj < 8; jj++) acc[i][jj] = 0;

            int4 pa = Ag[0];
            int4 pb = Bg[0];

            for (int s = 0; s < nstage; s++) {
                BAR_SYNC(2, 256);          // previous stage's reads done

                As[(wa + 0) * 128 + lrow] = pa.x;
                As[(wa + 1) * 128 + lrow] = pa.y;
                As[(wa + 2) * 128 + lrow] = pa.z;
                As[(wa + 3) * 128 + lrow] = pa.w;
                Bs[(wa + 0) * 128 + lrow] = pb.x;
                Bs[(wa + 1) * 128 + lrow] = pb.y;
                Bs[(wa + 2) * 128 + lrow] = pb.z;
                Bs[(wa + 3) * 128 + lrow] = pb.w;

                if (s + 1 < nstage) {
                    pa = Ag[(size_t)(s + 1) * 2];
                    pb = Bg[(size_t)(s + 1) * 2];
                }

                BAR_SYNC(2, 256);          // stores visible

#pragma unroll
                for (int kk = 0; kk < BKW; kk++) {
                    int4 af0 = *reinterpret_cast<const int4*>(&As[kk * 128 + (ty << 3)]);
                    int4 af1 = *reinterpret_cast<const int4*>(&As[kk * 128 + (ty << 3) + 4]);
                    int4 bf0 = *reinterpret_cast<const int4*>(&Bs[kk * 128 + (tx << 3)]);
                    int4 bf1 = *reinterpret_cast<const int4*>(&Bs[kk * 128 + (tx << 3) + 4]);
                    int af[8] = {af0.x, af0.y, af0.z, af0.w, af1.x, af1.y, af1.z, af1.w};
                    int bf[8] = {bf0.x, bf0.y, bf0.z, bf0.w, bf1.x, bf1.y, bf1.z, bf1.w};
#pragma unroll
                    for (int i = 0; i < 8; i++)
#pragma unroll
                        for (int jj = 0; jj < 8; jj++)
                            acc[i][jj] = __dp4a(af[i], bf[jj], acc[i][jj]);
                }
            }

            const int cn = bn_d + (tx << 3);
            float4 ws0 = *reinterpret_cast<const float4*>(wscale + cn);
            float4 ws1 = *reinterpret_cast<const float4*>(wscale + cn + 4);
            float4 bb0 = *reinterpret_cast<const float4*>(bias + cn);
            float4 bb1 = *reinterpret_cast<const float4*>(bias + cn + 4);
            float wsc[8] = {ws0.x, ws0.y, ws0.z, ws0.w, ws1.x, ws1.y, ws1.z, ws1.w};
            float bb[8]  = {bb0.x, bb0.y, bb0.z, bb0.w, bb1.x, bb1.y, bb1.z, bb1.w};

#pragma unroll
            for (int i = 0; i < 8; i++) {
                const int m = bm + (ty << 3) + i;
                const float xs = g_xscale[m];
                float* orow = out + (size_t)m * N + cn;
                float4 o0, o1;
                o0.x = (float)acc[i][0] * xs * wsc[0] + bb[0];
                o0.y = (float)acc[i][1] * xs * wsc[1] + bb[1];
                o0.z = (float)acc[i][2] * xs * wsc[2] + bb[2];
                o0.w = (float)acc[i][3] * xs * wsc[3] + bb[3];
                o1.x = (float)acc[i][4] * xs * wsc[4] + bb[4];
                o1.y = (float)acc[i][5] * xs * wsc[5] + bb[5];
                o1.z = (float)acc[i][6] * xs * wsc[6] + bb[6];
                o1.w = (float)acc[i][7] * xs * wsc[7] + bb[7];
                *reinterpret_cast<float4*>(orow)     = o0;
                *reinterpret_cast<float4*>(orow + 4) = o1;
            }
        }
    }
}

// ---------------------------------------------------------------------------
// Launch
// ---------------------------------------------------------------------------
extern "C" void kernel_launch(void* const* d_in, const int* in_sizes, int n_in,
                              void* d_out, int out_size) {
    const float* x      = (const float*)d_in[0];
    const int*   weight = (const int*)d_in[1];
    const float* wscale = (const float*)d_in[2];
    const float* bias   = (const float*)d_in[3];
    float*       out    = (float*)d_out;

    const int N = in_sizes[2];           // 11008
    const int K = in_sizes[1] / N;       // 4096
    const int M = in_sizes[0] / K;       // 4096

    detect_w_dtype<<<1, 32>>>(weight);

    const size_t n_out16 = ((size_t)N * K) / 16;
    pack_w<<<(unsigned)((n_out16 + 255) / 256), 256>>>(weight, n_out16);

    quant_rows<<<M, 256>>>(x, K);

    static int nsm = 0;
    if (!nsm) {
        cudaDeviceGetAttribute(&nsm, cudaDevAttrMultiProcessorCount, 0);
        if (nsm <= 0) nsm = 148;
        cudaFuncSetAttribute(gemm_hybrid,
                             cudaFuncAttributeMaxDynamicSharedMemorySize,
                             SM_TOTAL);
    }
    gemm_hybrid<<<nsm, 512, SM_TOTAL>>>(wscale, bias, out, M, N, K);
}

// round 12
// speedup vs baseline: 1.2116x; 1.0445x over previous
#include <cuda_runtime.h>
#include <cstdint>
#include <cstddef>

// ---------------------------------------------------------------------------
// W8A8 dynamic linear — persistent hybrid IMMA + dp4a, dynamic shared queue.
//   x [M,K] fp32 -> per-row dynamic int8 quant (scale = maxabs/127, >=1e-8)
//   weight [N,K] int8 (harness widens to int32; detected + packed)
//   out [M,N] fp32 = (xq @ wq^T) * x_scale[m] * w_scale[n] + bias[n]
// Static shapes: M=4096, K=4096, N=11008.
//
// Grid = #SMs, 512 threads/CTA. Warps 0-7 run the IMMA microkernel, warps
// 8-15 run the dp4a microkernel. BOTH halves pull 128x128 output-tile jobs
// from ONE global atomic counter — the faster pipe automatically does more
// tiles, so load balance is exact regardless of per-SM speed variation.
// Both microkernels produce identical results for any tile.
// ---------------------------------------------------------------------------

#define MAXM 4096
#define MAXK 4096
#define MAXN 11008

#define M_TILES 32                     // M/128
#define N_TILES 86                     // N/128
#define NJOBS (M_TILES * N_TILES)      // 2752

__device__ int8_t g_xq[(size_t)MAXM * MAXK];          // 16 MB
__device__ float  g_xscale[MAXM];
__device__ int8_t g_wq[(size_t)MAXN * MAXK];          // 43 MB
__device__ int    g_w_widened;
__device__ unsigned int g_job;                        // dynamic tile queue

// ------------------------------ helpers ------------------------------------
__device__ __forceinline__ uint32_t smem_u32(const void* p) {
    uint32_t a;
    asm("{ .reg .u64 t; cvta.to.shared.u64 t, %1; cvt.u32.u64 %0, t; }"
        : "=r"(a) : "l"(p));
    return a;
}

__device__ __forceinline__ uint32_t swz(uint32_t o) {   // SW128 swizzle
    return o ^ ((o >> 3) & 0x70);
}

__device__ __forceinline__ void cp_async16(uint32_t dst, const void* src) {
    asm volatile("cp.async.cg.shared.global [%0], [%1], 16;"
                 :: "r"(dst), "l"(src) : "memory");
}
#define CP_ASYNC_COMMIT() asm volatile("cp.async.commit_group;" ::: "memory")
#define CP_ASYNC_WAIT(n)  asm volatile("cp.async.wait_group %0;" :: "n"(n) : "memory")

#define BAR_SYNC(id, cnt) \
    asm volatile("bar.sync %0, %1;" :: "r"(id), "r"(cnt) : "memory")

__device__ __forceinline__ void ldsm_x4(uint32_t& r0, uint32_t& r1,
                                        uint32_t& r2, uint32_t& r3,
                                        uint32_t addr) {
    asm volatile("ldmatrix.sync.aligned.m8n8.x4.shared.b16 {%0,%1,%2,%3}, [%4];"
                 : "=r"(r0), "=r"(r1), "=r"(r2), "=r"(r3) : "r"(addr));
}

__device__ __forceinline__ void imma16832(int* d, const uint32_t* a,
                                          const uint32_t* b) {
    asm volatile(
        "mma.sync.aligned.m16n8k32.row.col.s32.s8.s8.s32 "
        "{%0,%1,%2,%3}, {%4,%5,%6,%7}, {%8,%9}, {%0,%1,%2,%3};"
        : "+r"(d[0]), "+r"(d[1]), "+r"(d[2]), "+r"(d[3])
        : "r"(a[0]), "r"(a[1]), "r"(a[2]), "r"(a[3]), "r"(b[0]), "r"(b[1]));
}

// ---------------------------------------------------------------------------
// Kernel 0a: detect weight dtype + reset the job counter.
// ---------------------------------------------------------------------------
__global__ void detect_w_dtype(const int* __restrict__ w) {
    if (threadIdx.x == 0) g_job = 0;
    int bad = 0;
    for (int i = threadIdx.x; i < 8192; i += 32) {
        int v = w[i];
        bad |= (v < -128 || v > 127) ? 1 : 0;
    }
#pragma unroll
    for (int o = 16; o > 0; o >>= 1)
        bad |= __shfl_xor_sync(0xffffffffu, bad, o);
    if (threadIdx.x == 0) g_w_widened = bad ? 0 : 1;
}

// ---------------------------------------------------------------------------
// Kernel 0b: pack weights int32 -> int8 (or copy if already packed).
// ---------------------------------------------------------------------------
__device__ __forceinline__ int pack4(int4 v) {
    return (v.x & 0xff) | ((v.y & 0xff) << 8) | ((v.z & 0xff) << 16) | (v.w << 24);
}

__global__ __launch_bounds__(256) void pack_w(const int* __restrict__ w,
                                              size_t n_out16) {
    const size_t i = (size_t)blockIdx.x * 256 + threadIdx.x;
    if (i >= n_out16) return;
    int4 outv;
    if (g_w_widened) {
        const int4* src = reinterpret_cast<const int4*>(w) + i * 4;
        outv.x = pack4(src[0]);
        outv.y = pack4(src[1]);
        outv.z = pack4(src[2]);
        outv.w = pack4(src[3]);
    } else {
        outv = reinterpret_cast<const int4*>(w)[i];
    }
    reinterpret_cast<int4*>(g_wq)[i] = outv;
}

// ---------------------------------------------------------------------------
// Kernel 1: per-row maxabs -> scale -> RNE quantize -> pack.
// ---------------------------------------------------------------------------
__global__ __launch_bounds__(256) void quant_rows(const float* __restrict__ x,
                                                  int K) {
    const int m = blockIdx.x;
    const int t = threadIdx.x;
    const int K4 = K >> 2;
    const float4* __restrict__ xrow =
        reinterpret_cast<const float4*>(x + (size_t)m * K);

    float amax = 0.0f;
    for (int i = t; i < K4; i += 256) {
        float4 v = xrow[i];
        amax = fmaxf(amax, fmaxf(fmaxf(fabsf(v.x), fabsf(v.y)),
                                 fmaxf(fabsf(v.z), fabsf(v.w))));
    }

    __shared__ float red[8];
#pragma unroll
    for (int o = 16; o > 0; o >>= 1)
        amax = fmaxf(amax, __shfl_xor_sync(0xffffffffu, amax, o));
    if ((t & 31) == 0) red[t >> 5] = amax;
    __syncthreads();
    if (t < 32) {
        float a = (t < 8) ? red[t] : 0.0f;
#pragma unroll
        for (int o = 4; o > 0; o >>= 1)
            a = fmaxf(a, __shfl_xor_sync(0xffffffffu, a, o));
        if (t == 0) red[0] = a;
    }
    __syncthreads();

    const float scale = fmaxf(red[0] / 127.0f, 1e-8f);
    if (t == 0) g_xscale[m] = scale;

    int* __restrict__ outw = reinterpret_cast<int*>(g_xq + (size_t)m * K);
    for (int i = t; i < K4; i += 256) {
        float4 v = xrow[i];
        int q0 = min(127, max(-128, __float2int_rn(v.x / scale)));
        int q1 = min(127, max(-128, __float2int_rn(v.y / scale)));
        int q2 = min(127, max(-128, __float2int_rn(v.z / scale)));
        int q3 = min(127, max(-128, __float2int_rn(v.w / scale)));
        outw[i] = (q0 & 0xff) | ((q1 & 0xff) << 8) | ((q2 & 0xff) << 16)
                | (q3 << 24);
    }
}

// ---------------------------------------------------------------------------
// Kernel 2: persistent hybrid GEMM with a single dynamic tile queue.
// SMEM: [0,64K) IMMA double-buffered tiles; [64K,72K) dp4a stages; +job slots.
// ---------------------------------------------------------------------------
#define TILE_BYTES (128 * 128)         // 16 KB
#define SM_A0  0
#define SM_B0  (SM_A0 + TILE_BYTES)
#define SM_A1  (SM_B0 + TILE_BYTES)
#define SM_B1  (SM_A1 + TILE_BYTES)
#define SM_D   (SM_B1 + TILE_BYTES)    // dp4a region: 2 x 4 KB
#define SM_JOB (SM_D + 8192)           // [0]: IMMA job slot, [1]: dp4a job slot
#define SM_TOTAL (SM_JOB + 32)

#define BKW 8    // dp4a: int32 words of K per stage (= 32 int8)

__global__ __launch_bounds__(512, 1)
void gemm_hybrid(const float* __restrict__ wscale,
                 const float* __restrict__ bias,
                 float* __restrict__ out,
                 int M, int N, int K) {
    extern __shared__ __align__(1024) char smem[];
    const uint32_t sbase = smem_u32(smem);
    volatile unsigned* jslot = reinterpret_cast<volatile unsigned*>(smem + SM_JOB);

    const int tid = threadIdx.x;

    if (tid < 256) {
        // ================= IMMA half (warps 0-7, tensor pipe) ==============
        const int t   = tid;
        const int wid = t >> 5;
        const int lid = t & 31;
        const int wm  = wid >> 2;             // 0..1
        const int wn  = wid & 3;              // 0..3

        const int cg = t & 7;
        const int r0 = t >> 3;
        const int Kw16 = K >> 4;

        const int4* Abase = reinterpret_cast<const int4*>(g_xq) + cg;
        const int4* Bbase = reinterpret_cast<const int4*>(g_wq) + cg;

        uint32_t sA_dst[2][4], sB_dst[2][4];
#pragma unroll
        for (int p = 0; p < 2; p++)
#pragma unroll
            for (int i = 0; i < 4; i++) {
                const uint32_t o =
                    swz((uint32_t)(r0 + 32 * i) * 128u + (uint32_t)cg * 16u);
                sA_dst[p][i] = sbase + (p ? SM_A1 : SM_A0) + o;
                sB_dst[p][i] = sbase + (p ? SM_B1 : SM_B0) + o;
            }

        const int nstage = K / 128;           // 32
        const int lrow_off = (lid & 7) + ((lid >> 3) & 1) * 8;
        const int lchunk   = lid >> 4;
        const int g   = lid >> 2;
        const int q   = lid & 3;

        int bm = 0, bn = 0;
        auto issue = [&](int kc) {
            const int4* Ag = Abase + (size_t)(kc * 8);
            const int4* Bg = Bbase + (size_t)(kc * 8);
            const int p = kc & 1;
#pragma unroll
            for (int i = 0; i < 4; i++) {
                cp_async16(sA_dst[p][i], Ag + (size_t)(bm + r0 + 32 * i) * Kw16);
                cp_async16(sB_dst[p][i], Bg + (size_t)(bn + r0 + 32 * i) * Kw16);
            }
            CP_ASYNC_COMMIT();
        };

        for (;;) {
            if (t == 0) jslot[0] = atomicAdd(&g_job, 1u);
            BAR_SYNC(1, 256);
            const unsigned j = jslot[0];
            if (j >= NJOBS) break;
            bm = (int)(j & (M_TILES - 1)) * 128;
            bn = (int)(j >> 5) * 128;

            int acc[4][4][4];
#pragma unroll
            for (int i = 0; i < 4; i++)
#pragma unroll
                for (int jj = 0; jj < 4; jj++)
#pragma unroll
                    for (int qq = 0; qq < 4; qq++) acc[i][jj][qq] = 0;

            issue(0);

            for (int kc = 0; kc < nstage; kc++) {
                if (kc + 1 < nstage) {
                    issue(kc + 1);
                    CP_ASYNC_WAIT(1);
                } else {
                    CP_ASYNC_WAIT(0);
                }
                BAR_SYNC(1, 256);

                const int p = kc & 1;
                const uint32_t sA = sbase + (p ? SM_A1 : SM_A0);
                const uint32_t sB = sbase + (p ? SM_B1 : SM_B0);

#pragma unroll
                for (int s = 0; s < 4; s++) {
                    const int c = s * 2 + lchunk;
                    uint32_t a[4][4];
#pragma unroll
                    for (int ma = 0; ma < 4; ma++) {
                        const uint32_t row =
                            (uint32_t)(wm * 64 + ma * 16 + lrow_off);
                        ldsm_x4(a[ma][0], a[ma][1], a[ma][2], a[ma][3],
                                sA + swz(row * 128u + (uint32_t)c * 16u));
                    }
                    uint32_t b[4][2];
#pragma unroll
                    for (int nb = 0; nb < 2; nb++) {
                        const uint32_t row =
                            (uint32_t)(wn * 32 + nb * 16 + lrow_off);
                        uint32_t q0, q1, q2, q3;
                        ldsm_x4(q0, q1, q2, q3,
                                sB + swz(row * 128u + (uint32_t)c * 16u));
                        b[2 * nb][0] = q0; b[2 * nb][1] = q2;
                        b[2 * nb + 1][0] = q1; b[2 * nb + 1][1] = q3;
                    }
#pragma unroll
                    for (int ma = 0; ma < 4; ma++)
#pragma unroll
                        for (int na = 0; na < 4; na++)
                            imma16832(acc[ma][na], a[ma], b[na]);
                }
                BAR_SYNC(1, 256);
            }

            // epilogue
#pragma unroll
            for (int ma = 0; ma < 4; ma++) {
                const int m0 = bm + wm * 64 + ma * 16 + g;
                const int m1 = m0 + 8;
                const float xs0 = g_xscale[m0];
                const float xs1 = g_xscale[m1];
                float* row0 = out + (size_t)m0 * N;
                float* row1 = out + (size_t)m1 * N;
#pragma unroll
                for (int na = 0; na < 4; na++) {
                    const int n = bn + wn * 32 + na * 8 + q * 2;
                    const float ws0 = __ldg(wscale + n);
                    const float ws1 = __ldg(wscale + n + 1);
                    const float bb0 = __ldg(bias + n);
                    const float bb1 = __ldg(bias + n + 1);
                    float2 o0, o1;
                    o0.x = (float)acc[ma][na][0] * xs0 * ws0 + bb0;
                    o0.y = (float)acc[ma][na][1] * xs0 * ws1 + bb1;
                    o1.x = (float)acc[ma][na][2] * xs1 * ws0 + bb0;
                    o1.y = (float)acc[ma][na][3] * xs1 * ws1 + bb1;
                    *reinterpret_cast<float2*>(row0 + n) = o0;
                    *reinterpret_cast<float2*>(row1 + n) = o1;
                }
            }
        }
    } else {
        // ================= dp4a half (warps 8-15, fma pipe) ================
        const int t = tid - 256;

        int* As = reinterpret_cast<int*>(smem + SM_D);          // [BKW][128]
        int* Bs = As + BKW * 128;                               // [BKW][128]

        const int tx = t & 15;
        const int ty = t >> 4;
        const int lrow = t & 127;          // SMEM row this thread fills
        const int cgd  = t >> 7;           // 0/1: 16B group
        const int wa   = cgd * 4;

        const int Kw16 = K >> 4;
        const int nstage = (K >> 2) / BKW; // 128 stages

        for (;;) {
            if (t == 0) jslot[1] = atomicAdd(&g_job, 1u);
            BAR_SYNC(2, 256);
            const unsigned j = jslot[1];
            if (j >= NJOBS) break;
            const int bm = (int)(j & (M_TILES - 1)) * 128;
            const int bn = (int)(j >> 5) * 128;

            const int4* Ag = reinterpret_cast<const int4*>(g_xq) +
                             (size_t)(bm + lrow) * Kw16 + cgd;
            const int4* Bg = reinterpret_cast<const int4*>(g_wq) +
                             (size_t)(bn + lrow) * Kw16 + cgd;

            int acc[8][8];
#pragma unroll
            for (int i = 0; i < 8; i++)
#pragma unroll
                for (int jj = 0; jj < 8; jj++) acc[i][jj] = 0;

            int4 pa = Ag[0];
            int4 pb = Bg[0];

            for (int s = 0; s < nstage; s++) {
                BAR_SYNC(2, 256);          // previous stage's reads done

                As[(wa + 0) * 128 + lrow] = pa.x;
                As[(wa + 1) * 128 + lrow] = pa.y;
                As[(wa + 2) * 128 + lrow] = pa.z;
                As[(wa + 3) * 128 + lrow] = pa.w;
                Bs[(wa + 0) * 128 + lrow] = pb.x;
                Bs[(wa + 1) * 128 + lrow] = pb.y;
                Bs[(wa + 2) * 128 + lrow] = pb.z;
                Bs[(wa + 3) * 128 + lrow] = pb.w;

                if (s + 1 < nstage) {
                    pa = Ag[(size_t)(s + 1) * 2];
                    pb = Bg[(size_t)(s + 1) * 2];
                }

                BAR_SYNC(2, 256);          // stores visible

#pragma unroll
                for (int kk = 0; kk < BKW; kk++) {
                    int4 af0 = *reinterpret_cast<const int4*>(&As[kk * 128 + (ty << 3)]);
                    int4 af1 = *reinterpret_cast<const int4*>(&As[kk * 128 + (ty << 3) + 4]);
                    int4 bf0 = *reinterpret_cast<const int4*>(&Bs[kk * 128 + (tx << 3)]);
                    int4 bf1 = *reinterpret_cast<const int4*>(&Bs[kk * 128 + (tx << 3) + 4]);
                    int af[8] = {af0.x, af0.y, af0.z, af0.w, af1.x, af1.y, af1.z, af1.w};
                    int bf[8] = {bf0.x, bf0.y, bf0.z, bf0.w, bf1.x, bf1.y, bf1.z, bf1.w};
#pragma unroll
                    for (int i = 0; i < 8; i++)
#pragma unroll
                        for (int jj = 0; jj < 8; jj++)
                            acc[i][jj] = __dp4a(af[i], bf[jj], acc[i][jj]);
                }
            }

            const int cn = bn + (tx << 3);
            float4 ws0 = *reinterpret_cast<const float4*>(wscale + cn);
            float4 ws1 = *reinterpret_cast<const float4*>(wscale + cn + 4);
            float4 bb0 = *reinterpret_cast<const float4*>(bias + cn);
            float4 bb1 = *reinterpret_cast<const float4*>(bias + cn + 4);
            float wsc[8] = {ws0.x, ws0.y, ws0.z, ws0.w, ws1.x, ws1.y, ws1.z, ws1.w};
            float bb[8]  = {bb0.x, bb0.y, bb0.z, bb0.w, bb1.x, bb1.y, bb1.z, bb1.w};

#pragma unroll
            for (int i = 0; i < 8; i++) {
                const int m = bm + (ty << 3) + i;
                const float xs = g_xscale[m];
                float* orow = out + (size_t)m * N + cn;
                float4 o0, o1;
                o0.x = (float)acc[i][0] * xs * wsc[0] + bb[0];
                o0.y = (float)acc[i][1] * xs * wsc[1] + bb[1];
                o0.z = (float)acc[i][2] * xs * wsc[2] + bb[2];
                o0.w = (float)acc[i][3] * xs * wsc[3] + bb[3];
                o1.x = (float)acc[i][4] * xs * wsc[4] + bb[4];
                o1.y = (float)acc[i][5] * xs * wsc[5] + bb[5];
                o1.z = (float)acc[i][6] * xs * wsc[6] + bb[6];
                o1.w = (float)acc[i][7] * xs * wsc[7] + bb[7];
                *reinterpret_cast<float4*>(orow)     = o0;
                *reinterpret_cast<float4*>(orow + 4) = o1;
            }
        }
    }
}

// ---------------------------------------------------------------------------
// Launch
// ---------------------------------------------------------------------------
extern "C" void kernel_launch(void* const* d_in, const int* in_sizes, int n_in,
                              void* d_out, int out_size) {
    const float* x      = (const float*)d_in[0];
    const int*   weight = (const int*)d_in[1];
    const float* wscale = (const float*)d_in[2];
    const float* bias   = (const float*)d_in[3];
    float*       out    = (float*)d_out;

    const int N = in_sizes[2];           // 11008
    const int K = in_sizes[1] / N;       // 4096
    const int M = in_sizes[0] / K;       // 4096

    detect_w_dtype<<<1, 32>>>(weight);   // also resets g_job

    const size_t n_out16 = ((size_t)N * K) / 16;
    pack_w<<<(unsigned)((n_out16 + 255) / 256), 256>>>(weight, n_out16);

    quant_rows<<<M, 256>>>(x, K);

    static int nsm = 0;
    if (!nsm) {
        cudaDeviceGetAttribute(&nsm, cudaDevAttrMultiProcessorCount, 0);
        if (nsm <= 0) nsm = 148;
        cudaFuncSetAttribute(gemm_hybrid,
                             cudaFuncAttributeMaxDynamicSharedMemorySize,
                             SM_TOTAL);
    }
    gemm_hybrid<<<nsm, 512, SM_TOTAL>>>(wscale, bias, out, M, N, K);
}